// round 1
// baseline (speedup 1.0000x reference)
#include <cuda_runtime.h>
#include <math.h>

#define Bdim 1024
#define Ndim 1024
#define Mdim 64
#define EPSV 1e-16f
#define COS_EPS 1e-8f

// Scratch (allocation-free rule: __device__ globals)
__device__ float g_dot[Bdim * Ndim];
__device__ float g_ssq[Bdim * Ndim];
__device__ float g_w[Bdim * Ndim];

// ---------------------------------------------------------------------------
// K1: per (b,n) row: dot((mem+eps), (k+eps)) and sum((mem+eps)^2)
// warp-per-row, 4 rows per warp for MLP.
// ---------------------------------------------------------------------------
__global__ void __launch_bounds__(256) k1_sim(const float* __restrict__ mem,
                                              const float* __restrict__ kk) {
    const int lane = threadIdx.x & 31;
    const int wid  = (blockIdx.x * blockDim.x + threadIdx.x) >> 5;
    const int row0 = wid * 4;                       // 4 consecutive rows
    if (row0 >= Bdim * Ndim) return;
    const int b = row0 >> 10;                       // row0 / Ndim (4 | 1024 => same b)

    float2 k2 = *(const float2*)(kk + b * Mdim + lane * 2);
    const float kx = k2.x + EPSV, ky = k2.y + EPSV;

    float dots[4], ssqs[4];
    const float* base = mem + (size_t)row0 * Mdim + lane * 2;
#pragma unroll
    for (int r = 0; r < 4; r++) {
        float2 m2 = *(const float2*)(base + (size_t)r * Mdim);
        float mx = m2.x + EPSV, my = m2.y + EPSV;
        dots[r] = mx * kx + my * ky;
        ssqs[r] = mx * mx + my * my;
    }
#pragma unroll
    for (int r = 0; r < 4; r++) {
#pragma unroll
        for (int o = 16; o > 0; o >>= 1) {
            dots[r] += __shfl_xor_sync(0xffffffffu, dots[r], o);
            ssqs[r] += __shfl_xor_sync(0xffffffffu, ssqs[r], o);
        }
    }
    if (lane < 4) {                                  // lane r writes row0+r
        g_dot[row0 + lane] = dots[lane];             // values uniform post-reduce
        g_ssq[row0 + lane] = ssqs[lane];
    }
}

// ---------------------------------------------------------------------------
// K2: per-b addressing pipeline: cosine score -> softmax -> interpolate ->
// circular 3-tap shift -> sharpen -> normalize. One 1024-thread block per b.
// ---------------------------------------------------------------------------
__global__ void __launch_bounds__(1024) k2_addr(const float* __restrict__ kk,
                                                const float* __restrict__ beta,
                                                const float* __restrict__ gg,
                                                const float* __restrict__ ss,
                                                const float* __restrict__ gamma,
                                                const float* __restrict__ wprev) {
    const int b = blockIdx.x;
    const int n = threadIdx.x;

    __shared__ float sh[Ndim];
    __shared__ float swg[Ndim];
    __shared__ float s_knorm;

    // k norm (64 elems)
    if (n < Mdim) {
        float kv = kk[b * Mdim + n] + EPSV;
        sh[n] = kv * kv;
    }
    __syncthreads();
    if (n == 0) {
        float t = 0.f;
#pragma unroll
        for (int i = 0; i < Mdim; i++) t += sh[i];
        s_knorm = fmaxf(sqrtf(t), COS_EPS);
    }
    __syncthreads();

    const float dot = g_dot[b * Ndim + n];
    const float nrm = fmaxf(sqrtf(g_ssq[b * Ndim + n]), COS_EPS);
    float score = beta[b] * (dot / (nrm * s_knorm));

    // block max
    sh[n] = score; __syncthreads();
#pragma unroll
    for (int s = 512; s > 0; s >>= 1) {
        if (n < s) sh[n] = fmaxf(sh[n], sh[n + s]);
        __syncthreads();
    }
    const float mx = sh[0]; __syncthreads();

    float ex = expf(score - mx);
    sh[n] = ex; __syncthreads();
#pragma unroll
    for (int s = 512; s > 0; s >>= 1) {
        if (n < s) sh[n] += sh[n + s];
        __syncthreads();
    }
    const float esum = sh[0]; __syncthreads();
    const float wc = ex / esum;

    // interpolate
    const float gv = gg[b];
    const float wgv = gv * wc + (1.f - gv) * wprev[b * Ndim + n];
    swg[n] = wgv;
    __syncthreads();

    // circular shift
    const float s0 = ss[b * 3 + 0], s1 = ss[b * 3 + 1], s2 = ss[b * 3 + 2];
    float wh = s0 * swg[(n + Ndim - 1) & (Ndim - 1)]
             + s1 * wgv
             + s2 * swg[(n + 1) & (Ndim - 1)];

    // sharpen
    float w = powf(wh, gamma[b]);
    sh[n] = w; __syncthreads();
#pragma unroll
    for (int s = 512; s > 0; s >>= 1) {
        if (n < s) sh[n] += sh[n + s];
        __syncthreads();
    }
    const float wsum = sh[0];

    g_w[b * Ndim + n] = w / (wsum + EPSV);
}

// ---------------------------------------------------------------------------
// K3: read vector + erase/add write. One block per b; 512 threads =
// 16 row-groups x 32 m-lanes (float2 each).
// ---------------------------------------------------------------------------
__global__ void __launch_bounds__(512) k3_rw(const float* __restrict__ mem,
                                             const float* __restrict__ ee,
                                             const float* __restrict__ aa,
                                             float* __restrict__ out) {
    const int b   = blockIdx.x;
    const int tid = threadIdx.x;
    const int mh  = tid & 31;        // m-pair lane
    const int rg  = tid >> 5;        // row group 0..15

    __shared__ float sw[Ndim];
    for (int i = tid; i < Ndim; i += 512) sw[i] = g_w[b * Ndim + i];

    const float2 e2 = *(const float2*)(ee + b * Mdim + mh * 2);
    const float2 a2 = *(const float2*)(aa + b * Mdim + mh * 2);
    __syncthreads();

    const float* mb = mem + (size_t)b * Ndim * Mdim;
    float* ob       = out + (size_t)b * (Ndim + 1) * Mdim;

    float rx = 0.f, ry = 0.f;
#pragma unroll 4
    for (int base = 0; base < Ndim; base += 16) {
        const int n = base + rg;
        const float wv = sw[n];
        float2 m2 = *(const float2*)(mb + n * Mdim + mh * 2);
        float2 o2;
        o2.x = m2.x * (1.f - wv * e2.x) + wv * a2.x;
        o2.y = m2.y * (1.f - wv * e2.y) + wv * a2.y;
        *(float2*)(ob + (size_t)(1 + n) * Mdim + mh * 2) = o2;
        rx += wv * m2.x;
        ry += wv * m2.y;
    }

    // reduce read accumulators over the 16 row groups (stride-32 tree)
    __shared__ float srx[512];
    __shared__ float sry[512];
    srx[tid] = rx; sry[tid] = ry;
    __syncthreads();
#pragma unroll
    for (int s = 256; s >= 32; s >>= 1) {
        if (tid < s) { srx[tid] += srx[tid + s]; sry[tid] += sry[tid + s]; }
        __syncthreads();
    }
    if (tid < 32) {
        float2 o2; o2.x = srx[tid]; o2.y = sry[tid];
        *(float2*)(ob + tid * 2) = o2;              // read row (row 0)
    }
}

// ---------------------------------------------------------------------------
extern "C" void kernel_launch(void* const* d_in, const int* in_sizes, int n_in,
                              void* d_out, int out_size) {
    const float* mem   = (const float*)d_in[0];
    const float* kk    = (const float*)d_in[1];
    const float* beta  = (const float*)d_in[2];
    const float* gg    = (const float*)d_in[3];
    const float* ss    = (const float*)d_in[4];
    const float* gamma = (const float*)d_in[5];
    const float* wprev = (const float*)d_in[6];
    const float* ee    = (const float*)d_in[7];
    const float* aa    = (const float*)d_in[8];
    float* out = (float*)d_out;

    // K1: 8 warps/block * 4 rows/warp = 32 rows/block
    k1_sim<<<(Bdim * Ndim) / 32, 256>>>(mem, kk);
    k2_addr<<<Bdim, 1024>>>(kk, beta, gg, ss, gamma, wprev);
    k3_rw<<<Bdim, 512>>>(mem, ee, aa, out);
}

// round 2
// speedup vs baseline: 1.1079x; 1.1079x over previous
#include <cuda_runtime.h>
#include <math.h>

#define Bdim 1024
#define Ndim 1024
#define Mdim 64
#define EPSV 1e-16f
#define COS_EPS 1e-8f

// Scratch (allocation-free rule: __device__ globals)
__device__ float2 g_ds[Bdim * Ndim];   // (dot, ssq) interleaved
__device__ float  g_w [Bdim * Ndim];

// ---------------------------------------------------------------------------
// K1: per (b,n) row: dot((mem+eps),(k+eps)) and sum((mem+eps)^2).
// float4 loads: 16 lanes per row, 2 rows per warp-load, 8 rows per warp.
// ---------------------------------------------------------------------------
__global__ void __launch_bounds__(256) k1_sim(const float* __restrict__ mem,
                                              const float* __restrict__ kk) {
    const int lane = threadIdx.x & 31;
    const int wid  = (blockIdx.x * blockDim.x + threadIdx.x) >> 5;
    const int row0 = wid * 8;                      // 8 rows per warp
    const int b    = row0 >> 10;                   // 8 | 1024 => same b
    const int sub  = lane & 15;                    // position within row
    const int half = lane >> 4;                    // row parity within pair

    float4 k4 = *(const float4*)(kk + b * Mdim + sub * 4);
    const float kx = k4.x + EPSV, ky = k4.y + EPSV;
    const float kz = k4.z + EPSV, kw = k4.w + EPSV;

    const float* base = mem + (size_t)(row0 + half) * Mdim + sub * 4;
    float4 m[4];
#pragma unroll
    for (int r = 0; r < 4; r++)
        m[r] = *(const float4*)(base + (size_t)(2 * r) * Mdim);

    float dots[4], ssqs[4];
#pragma unroll
    for (int r = 0; r < 4; r++) {
        float ax = m[r].x + EPSV, ay = m[r].y + EPSV;
        float az = m[r].z + EPSV, aw = m[r].w + EPSV;
        float d = ax * kx; d = fmaf(ay, ky, d); d = fmaf(az, kz, d); d = fmaf(aw, kw, d);
        float s = ax * ax; s = fmaf(ay, ay, s); s = fmaf(az, az, s); s = fmaf(aw, aw, s);
        dots[r] = d; ssqs[r] = s;
    }
#pragma unroll
    for (int r = 0; r < 4; r++) {
#pragma unroll
        for (int o = 8; o > 0; o >>= 1) {          // reduce within 16-lane group
            dots[r] += __shfl_xor_sync(0xffffffffu, dots[r], o);
            ssqs[r] += __shfl_xor_sync(0xffffffffu, ssqs[r], o);
        }
    }
    if (sub == 0) {                                // lanes 0 and 16 write rows
#pragma unroll
        for (int r = 0; r < 4; r++)
            g_ds[row0 + 2 * r + half] = make_float2(dots[r], ssqs[r]);
    }
}

// ---------------------------------------------------------------------------
// K2: cosine score -> softmax -> interpolate -> circular 3-tap shift ->
// sharpen -> normalize. One 1024-thread block per b, shuffle reductions.
// ---------------------------------------------------------------------------
__device__ __forceinline__ float block_reduce(float v, float* red, int n,
                                              bool is_max) {
    const int lane = n & 31, warp = n >> 5;
#pragma unroll
    for (int o = 16; o > 0; o >>= 1) {
        float t = __shfl_xor_sync(0xffffffffu, v, o);
        v = is_max ? fmaxf(v, t) : (v + t);
    }
    if (lane == 0) red[warp] = v;
    __syncthreads();
    if (warp == 0) {
        float t = red[lane];
#pragma unroll
        for (int o = 16; o > 0; o >>= 1) {
            float u = __shfl_xor_sync(0xffffffffu, t, o);
            t = is_max ? fmaxf(t, u) : (t + u);
        }
        if (lane == 0) red[0] = t;
    }
    __syncthreads();
    return red[0];
}

__global__ void __launch_bounds__(1024) k2_addr(const float* __restrict__ kk,
                                                const float* __restrict__ beta,
                                                const float* __restrict__ gg,
                                                const float* __restrict__ ss,
                                                const float* __restrict__ gamma,
                                                const float* __restrict__ wprev) {
    const int b = blockIdx.x;
    const int n = threadIdx.x;
    const int lane = n & 31, warp = n >> 5;

    __shared__ float red[32];
    __shared__ float swg[Ndim];
    __shared__ float s_knorm;

    // k norm: warp 0 (each lane covers 2 elements)
    if (warp == 0) {
        float kv1 = kk[b * Mdim + lane] + EPSV;
        float kv2 = kk[b * Mdim + 32 + lane] + EPSV;
        float t = kv1 * kv1 + kv2 * kv2;
#pragma unroll
        for (int o = 16; o > 0; o >>= 1) t += __shfl_xor_sync(0xffffffffu, t, o);
        if (lane == 0) s_knorm = fmaxf(sqrtf(t), COS_EPS);
    }
    const float2 ds = g_ds[b * Ndim + n];
    __syncthreads();

    const float nrm = fmaxf(sqrtf(ds.y), COS_EPS);
    const float score = beta[b] * (ds.x / (nrm * s_knorm));

    const float mx = block_reduce(score, red, n, true);
    __syncthreads();
    const float ex = __expf(score - mx);
    const float esum = block_reduce(ex, red, n, false);
    const float wc = ex / esum;

    // interpolate
    const float gv = gg[b];
    const float wgv = fmaf(gv, wc - wprev[b * Ndim + n], wprev[b * Ndim + n]);
    swg[n] = wgv;
    __syncthreads();

    // circular shift
    const float s0 = ss[b * 3 + 0], s1 = ss[b * 3 + 1], s2 = ss[b * 3 + 2];
    const float wh = s0 * swg[(n + Ndim - 1) & (Ndim - 1)]
                   + s1 * wgv
                   + s2 * swg[(n + 1) & (Ndim - 1)];

    // sharpen
    const float w = __powf(wh, gamma[b]);
    __syncthreads();
    const float wsum = block_reduce(w, red, n, false);

    g_w[b * Ndim + n] = w / (wsum + EPSV);
}

// ---------------------------------------------------------------------------
// K3: read vector + erase/add write. One block per b; 512 threads =
// 32 row-groups x 16 m-lanes (float4 each).
// ---------------------------------------------------------------------------
__global__ void __launch_bounds__(512) k3_rw(const float* __restrict__ mem,
                                             const float* __restrict__ ee,
                                             const float* __restrict__ aa,
                                             float* __restrict__ out) {
    const int b   = blockIdx.x;
    const int tid = threadIdx.x;
    const int ml  = tid & 15;        // m-quad lane
    const int rg  = tid >> 4;        // row group 0..31

    __shared__ float sw[Ndim];
    for (int i = tid; i < Ndim; i += 512) sw[i] = g_w[b * Ndim + i];

    const float4 e4 = *(const float4*)(ee + b * Mdim + ml * 4);
    const float4 a4 = *(const float4*)(aa + b * Mdim + ml * 4);
    __syncthreads();

    const float* mb = mem + (size_t)b * Ndim * Mdim;
    float* ob       = out + (size_t)b * (Ndim + 1) * Mdim;

    float rx = 0.f, ry = 0.f, rz = 0.f, rw = 0.f;
#pragma unroll 4
    for (int base = 0; base < Ndim; base += 32) {
        const int n = base + rg;
        const float wv = sw[n];
        float4 m4 = *(const float4*)(mb + n * Mdim + ml * 4);
        float4 o4;
        o4.x = fmaf(m4.x, fmaf(-wv, e4.x, 1.f), wv * a4.x);
        o4.y = fmaf(m4.y, fmaf(-wv, e4.y, 1.f), wv * a4.y);
        o4.z = fmaf(m4.z, fmaf(-wv, e4.z, 1.f), wv * a4.z);
        o4.w = fmaf(m4.w, fmaf(-wv, e4.w, 1.f), wv * a4.w);
        *(float4*)(ob + (size_t)(1 + n) * Mdim + ml * 4) = o4;
        rx = fmaf(wv, m4.x, rx);
        ry = fmaf(wv, m4.y, ry);
        rz = fmaf(wv, m4.z, rz);
        rw = fmaf(wv, m4.w, rw);
    }

    // reduce read accumulators over the 32 row groups (stride-16 tree)
    __shared__ float4 sr[512];
    sr[tid] = make_float4(rx, ry, rz, rw);
    __syncthreads();
#pragma unroll
    for (int s = 256; s >= 16; s >>= 1) {
        if (tid < s) {
            float4 x = sr[tid], y = sr[tid + s];
            x.x += y.x; x.y += y.y; x.z += y.z; x.w += y.w;
            sr[tid] = x;
        }
        __syncthreads();
    }
    if (tid < 16) *(float4*)(ob + tid * 4) = sr[tid];   // read row (row 0)
}

// ---------------------------------------------------------------------------
extern "C" void kernel_launch(void* const* d_in, const int* in_sizes, int n_in,
                              void* d_out, int out_size) {
    const float* mem   = (const float*)d_in[0];
    const float* kk    = (const float*)d_in[1];
    const float* beta  = (const float*)d_in[2];
    const float* gg    = (const float*)d_in[3];
    const float* ss    = (const float*)d_in[4];
    const float* gamma = (const float*)d_in[5];
    const float* wprev = (const float*)d_in[6];
    const float* ee    = (const float*)d_in[7];
    const float* aa    = (const float*)d_in[8];
    float* out = (float*)d_out;

    // K1: 8 warps/block * 8 rows/warp = 64 rows/block
    k1_sim<<<(Bdim * Ndim) / 64, 256>>>(mem, kk);
    k2_addr<<<Bdim, 1024>>>(kk, beta, gg, ss, gamma, wprev);
    k3_rw<<<Bdim, 512>>>(mem, ee, aa, out);
}